// round 16
// baseline (speedup 1.0000x reference)
#include <cuda_runtime.h>
#include <cuda_bf16.h>
#include <cstdint>

#define NNODES 255
#define BATCH  256
#define MROWS  (NNODES * BATCH)   // 65280
#define ELL_CAP 64
#define MAX_NNZ 2048
#define KP_MAX  416

// ---------------------------------------------------------------------------
// Scratch (no cudaMalloc allowed)
// ---------------------------------------------------------------------------
__device__ __align__(128) float          g_y   [MROWS * 304];        // Form-O GEMM out
__device__ __align__(128) float          g_xf  [MROWS * 400];        // fp32 activations
__device__ __align__(128) __nv_bfloat16  g_uh  [MROWS * KP_MAX];     // GEMM A hi
__device__ __align__(128) __nv_bfloat16  g_ul  [MROWS * KP_MAX];     // GEMM A lo
__device__ __align__(128) __nv_bfloat16  g_wth [4 * 400 * KP_MAX];
__device__ __align__(128) __nv_bfloat16  g_wtl [4 * 400 * KP_MAX];
__device__ __align__(128) float          g_sa  [MROWS * 2];
__device__ float g_ell_vals[4 * NNODES * ELL_CAP];
__device__ int   g_ell_cols[4 * NNODES * ELL_CAP];
__device__ int   g_ell_cnt [4 * NNODES];
__device__ float g_rowsum  [4 * NNODES];

// ---------------------------------------------------------------------------
// PTX helpers (family-neutral)
// ---------------------------------------------------------------------------
__device__ __forceinline__ uint32_t smem_u32(const void* p) {
    uint32_t a;
    asm("{ .reg .u64 t; cvta.to.shared.u64 t, %1; cvt.u32.u64 %0, t; }"
        : "=r"(a) : "l"(p));
    return a;
}
__device__ __forceinline__ void cp16(uint32_t dst, const void* src, uint32_t bytes) {
    asm volatile("cp.async.cg.shared.global [%0], [%1], 16, %2;"
                 :: "r"(dst), "l"(src), "r"(bytes) : "memory");
}
#define CP_COMMIT() asm volatile("cp.async.commit_group;" ::: "memory")
#define CP_WAIT(n)  asm volatile("cp.async.wait_group %0;" :: "n"(n) : "memory")

__device__ __forceinline__ void ldsm4(uint32_t* r, uint32_t addr) {
    asm volatile("ldmatrix.sync.aligned.m8n8.x4.shared.b16 {%0,%1,%2,%3}, [%4];"
                 : "=r"(r[0]), "=r"(r[1]), "=r"(r[2]), "=r"(r[3]) : "r"(addr));
}
__device__ __forceinline__ void ldsm2(uint32_t* r, uint32_t addr) {
    asm volatile("ldmatrix.sync.aligned.m8n8.x2.shared.b16 {%0,%1}, [%2];"
                 : "=r"(r[0]), "=r"(r[1]) : "r"(addr));
}
__device__ __forceinline__ void mma16816(float* c, const uint32_t* a, const uint32_t* b) {
    asm volatile("mma.sync.aligned.m16n8k16.row.col.f32.bf16.bf16.f32 "
                 "{%0,%1,%2,%3}, {%4,%5,%6,%7}, {%8,%9}, {%0,%1,%2,%3};"
                 : "+f"(c[0]), "+f"(c[1]), "+f"(c[2]), "+f"(c[3])
                 : "r"(a[0]), "r"(a[1]), "r"(a[2]), "r"(a[3]), "r"(b[0]), "r"(b[1]));
}
__device__ __forceinline__ uint32_t split_pack_hi(float v0, float v1, uint32_t& lo_bits) {
    __nv_bfloat162 h = __floats2bfloat162_rn(v0, v1);
    float2 hf = __bfloat1622float2(h);
    __nv_bfloat162 l = __floats2bfloat162_rn(v0 - hf.x, v1 - hf.y);
    lo_bits = *reinterpret_cast<uint32_t*>(&l);
    return *reinterpret_cast<uint32_t*>(&h);
}

// ---------------------------------------------------------------------------
// bf16x3 HMMA GEMM: CTA 128x64x32, 256 thr / 8 warps (4m x 2n), warp 32x32,
// 3-stage cp.async pipeline, 2 CTAs/SM. Next-stage loads issued BEFORE the
// compute loop (slot of blk+2 == slot of blk-1, free after the sync).
// FORMI=false: Y = A@B^T + bias ; FORMI=true: Y = relu(A@B^T + s[node]*bias).
// ---------------------------------------------------------------------------
#define BM 128
#define BN 64
#define LDT 40
#define MAT_A (128 * LDT * 2)          // 10240
#define MAT_Bt (64 * LDT * 2)          // 5120
#define STAGE_B (2 * MAT_A + 2 * MAT_Bt)   // 30720
#define NSTAGE 3

template <bool FORMI>
__global__ __launch_bounds__(256, 2)
void gemm_bf16x3_mma(const __nv_bfloat16* __restrict__ Ah,
                     const __nv_bfloat16* __restrict__ Al,
                     const __nv_bfloat16* __restrict__ Bh,
                     const __nv_bfloat16* __restrict__ Bl,
                     const float* __restrict__ bias,
                     const float* __restrict__ srow,
                     float* __restrict__ Y,
                     int Nfull, int Kp) {
    extern __shared__ __align__(128) char smem[];
    const uint32_t sb = smem_u32(smem);

    const int tid  = threadIdx.x;
    const int lane = tid & 31;
    const int wid  = tid >> 5;
    const int wm   = wid & 3;
    const int wn   = wid >> 2;
    const int m0   = blockIdx.y * BM;
    const int n0   = blockIdx.x * BN;

    const int nblk = Kp >> 5;

    auto load_stage = [&](int blk, int slot) {
        const int k0 = blk << 5;
        const uint32_t sdst = sb + slot * STAGE_B;
        #pragma unroll
        for (int i = 0; i < 6; i++) {
            const int idx = i * 256 + tid;          // 0..1535
            if (idx < 1024) {
                const int mat = idx >> 9;
                const int c   = idx & 511;
                const int row = c >> 2;
                const int seg = c & 3;
                const uint32_t dst = sdst + mat * MAT_A + (row * LDT + seg * 8) * 2;
                const __nv_bfloat16* src = (mat == 0 ? Ah : Al);
                cp16(dst, src + (size_t)(m0 + row) * Kp + k0 + seg * 8, 16);
            } else {
                const int j   = idx - 1024;
                const int mat = j >> 8;
                const int c   = j & 255;
                const int row = c >> 2;
                const int seg = c & 3;
                const uint32_t dst = sdst + 2 * MAT_A + mat * MAT_Bt +
                                     (row * LDT + seg * 8) * 2;
                const __nv_bfloat16* src = (mat == 0 ? Bh : Bl);
                const int gr = n0 + row;
                const int ok = gr < Nfull;
                cp16(dst, src + (size_t)(ok ? gr : 0) * Kp + k0 + seg * 8, ok ? 16 : 0);
            }
        }
        CP_COMMIT();
    };

    float acc[2][4][4];
    #pragma unroll
    for (int i = 0; i < 2; i++)
        #pragma unroll
        for (int j = 0; j < 4; j++)
            #pragma unroll
            for (int q = 0; q < 4; q++) acc[i][j][q] = 0.0f;

    #pragma unroll
    for (int s = 0; s < NSTAGE - 1; s++)
        if (s < nblk) load_stage(s, s);

    for (int blk = 0; blk < nblk; blk++) {
        int slot = blk % NSTAGE;
        if (blk + 1 < nblk) CP_WAIT(1);
        else                CP_WAIT(0);
        __syncthreads();

        // Early issue: loads for blk+2 overlap the whole compute phase.
        const int nx = blk + NSTAGE - 1;
        if (nx < nblk) load_stage(nx, nx % NSTAGE);

        const uint32_t stage = sb + slot * STAGE_B;
        #pragma unroll
        for (int ks = 0; ks < 32; ks += 16) {
            uint32_t ah[2][4], al[2][4], bh[4][2], bl[4][2];
            const int arow = wm * 32 + (lane & 15);
            const int akoff = ks + ((lane >> 4) << 3);
            #pragma unroll
            for (int mi = 0; mi < 2; mi++) {
                const uint32_t off = ((arow + mi * 16) * LDT + akoff) * 2;
                ldsm4(ah[mi], stage + off);
                ldsm4(al[mi], stage + MAT_A + off);
            }
            const int brow = wn * 32 + (lane & 7);
            const int bkoff = ks + (((lane >> 3) & 1) << 3);
            #pragma unroll
            for (int ni = 0; ni < 4; ni++) {
                const uint32_t off = ((brow + ni * 8) * LDT + bkoff) * 2;
                ldsm2(bh[ni], stage + 2 * MAT_A + off);
                ldsm2(bl[ni], stage + 2 * MAT_A + MAT_Bt + off);
            }
            #pragma unroll
            for (int mi = 0; mi < 2; mi++)
                #pragma unroll
                for (int ni = 0; ni < 4; ni++) {
                    mma16816(acc[mi][ni], ah[mi], bh[ni]);
                    mma16816(acc[mi][ni], ah[mi], bl[ni]);
                    mma16816(acc[mi][ni], al[mi], bh[ni]);
                }
        }
    }

    const float s = FORMI ? srow[m0 >> 8] : 0.0f;
    #pragma unroll
    for (int ni = 0; ni < 4; ni++) {
        const int gc = n0 + wn * 32 + ni * 8 + (lane & 3) * 2;
        if (gc >= Nfull) continue;
        const float b0 = FORMI ? s * bias[gc]     : bias[gc];
        const float b1 = FORMI ? s * bias[gc + 1] : bias[gc + 1];
        #pragma unroll
        for (int mi = 0; mi < 2; mi++) {
            const int gr = m0 + wm * 32 + mi * 16 + (lane >> 2);
            float2 v0 = make_float2(acc[mi][ni][0] + b0, acc[mi][ni][1] + b1);
            float2 v1 = make_float2(acc[mi][ni][2] + b0, acc[mi][ni][3] + b1);
            if (FORMI) {
                v0.x = fmaxf(v0.x, 0.f); v0.y = fmaxf(v0.y, 0.f);
                v1.x = fmaxf(v1.x, 0.f); v1.y = fmaxf(v1.y, 0.f);
            }
            *(float2*)(Y + (size_t)gr * Nfull + gc) = v0;
            *(float2*)(Y + (size_t)(gr + 8) * Nfull + gc) = v1;
        }
    }
}

// ---------------------------------------------------------------------------
// Gather spmm (fp32 in) -> split bf16 out
// ---------------------------------------------------------------------------
template <bool RELU>
__global__ __launch_bounds__(256)
void spmm_f32_split_kernel(const float* __restrict__ evals, const int* __restrict__ ecols,
                           const int* __restrict__ cnt, const float* __restrict__ X,
                           int din, int dis, int kp,
                           __nv_bfloat16* __restrict__ uh, __nv_bfloat16* __restrict__ ul) {
    const int r = blockIdx.y;
    const int n = cnt[r];
    __shared__ float sv[ELL_CAP];
    __shared__ int   sc[ELL_CAP];
    if (threadIdx.x < n) {
        sv[threadIdx.x] = evals[r * ELL_CAP + threadIdx.x];
        sc[threadIdx.x] = ecols[r * ELL_CAP + threadIdx.x];
    }
    __syncthreads();

    const int nF4 = kp >> 2;
    const int p = blockIdx.x * 256 + threadIdx.x;
    if (p >= BATCH * nF4) return;
    const int b = p / nF4, f = (p - b * nF4) * 4;
    const size_t obase = ((size_t)r * BATCH + b) * kp + f;

    if (f >= din) {
        *(uint2*)(uh + obase) = make_uint2(0, 0);
        *(uint2*)(ul + obase) = make_uint2(0, 0);
        return;
    }
    float4 acc = make_float4(0.f, 0.f, 0.f, 0.f);
    for (int j = 0; j < n; j++) {
        const float a = sv[j];
        const float4 x = *(const float4*)(X + ((size_t)sc[j] * BATCH + b) * dis + f);
        acc.x = fmaf(a, x.x, acc.x);
        acc.y = fmaf(a, x.y, acc.y);
        acc.z = fmaf(a, x.z, acc.z);
        acc.w = fmaf(a, x.w, acc.w);
    }
    if (RELU) {
        acc.x = fmaxf(acc.x, 0.f); acc.y = fmaxf(acc.y, 0.f);
        acc.z = fmaxf(acc.z, 0.f); acc.w = fmaxf(acc.w, 0.f);
    }
    uint32_t lo0, lo1;
    uint32_t hi0 = split_pack_hi(acc.x, acc.y, lo0);
    uint32_t hi1 = split_pack_hi(acc.z, acc.w, lo1);
    *(uint2*)(uh + obase) = make_uint2(hi0, hi1);
    *(uint2*)(ul + obase) = make_uint2(lo0, lo1);
}

// ---------------------------------------------------------------------------
// Gather spmm fp32 -> fp32 (+relu)
// ---------------------------------------------------------------------------
__global__ __launch_bounds__(256)
void spmm_relu_f32_kernel(const float* __restrict__ evals, const int* __restrict__ ecols,
                          const int* __restrict__ cnt, const float* __restrict__ Y,
                          int din, float* __restrict__ Xo) {
    const int r = blockIdx.y;
    const int n = cnt[r];
    __shared__ float sv[ELL_CAP];
    __shared__ int   sc[ELL_CAP];
    if (threadIdx.x < n) {
        sv[threadIdx.x] = evals[r * ELL_CAP + threadIdx.x];
        sc[threadIdx.x] = ecols[r * ELL_CAP + threadIdx.x];
    }
    __syncthreads();

    const int nF4 = din >> 2;
    const int p = blockIdx.x * 256 + threadIdx.x;
    if (p >= BATCH * nF4) return;
    const int b = p / nF4, f = (p - b * nF4) * 4;

    float4 acc = make_float4(0.f, 0.f, 0.f, 0.f);
    for (int j = 0; j < n; j++) {
        const float a = sv[j];
        const float4 x = *(const float4*)(Y + ((size_t)sc[j] * BATCH + b) * din + f);
        acc.x = fmaf(a, x.x, acc.x);
        acc.y = fmaf(a, x.y, acc.y);
        acc.z = fmaf(a, x.z, acc.z);
        acc.w = fmaf(a, x.w, acc.w);
    }
    acc.x = fmaxf(acc.x, 0.f); acc.y = fmaxf(acc.y, 0.f);
    acc.z = fmaxf(acc.z, 0.f); acc.w = fmaxf(acc.w, 0.f);
    *(float4*)(Xo + ((size_t)r * BATCH + b) * din + f) = acc;
}

// ---------------------------------------------------------------------------
// L5: Y[m,0:2] = xf[m, 0:400] @ Wd2[400,2] + bd2
// ---------------------------------------------------------------------------
__global__ __launch_bounds__(256)
void l5_kernel(const float* __restrict__ xf,
               const float* __restrict__ W, const float* __restrict__ bias,
               float* __restrict__ Y) {
    __shared__ float2 Ws[400];
    for (int i = threadIdx.x; i < 400; i += 256)
        Ws[i] = make_float2(W[i * 2], W[i * 2 + 1]);
    __syncthreads();

    const int m = blockIdx.x * 256 + threadIdx.x;
    const float* px = xf + (size_t)m * 400;
    float a0 = bias[0], a1 = bias[1];
    #pragma unroll 4
    for (int k = 0; k < 400; k += 4) {
        const float4 x = *(const float4*)(px + k);
        const float2 w0 = Ws[k], w1 = Ws[k + 1], w2 = Ws[k + 2], w3 = Ws[k + 3];
        a0 = fmaf(x.x, w0.x, a0); a1 = fmaf(x.x, w0.y, a1);
        a0 = fmaf(x.y, w1.x, a0); a1 = fmaf(x.y, w1.y, a1);
        a0 = fmaf(x.z, w2.x, a0); a1 = fmaf(x.z, w2.y, a1);
        a0 = fmaf(x.w, w3.x, a0); a1 = fmaf(x.w, w3.y, a1);
    }
    *(float2*)(Y + (size_t)m * 2) = make_float2(a0, a1);
}

// ---------------------------------------------------------------------------
// Weight prep (all 4 weights, one launch)
// ---------------------------------------------------------------------------
__global__ void wt_split4_kernel(const float* W0_, const float* W1_,
                                 const float* W2_, const float* W3_,
                                 __nv_bfloat16* __restrict__ wh,
                                 __nv_bfloat16* __restrict__ wl) {
    const int t = blockIdx.y;
    const int tK[4]  = {400, 300, 100, 300};
    const int tN[4]  = {300, 100, 300, 400};
    const int tKp[4] = {416, 320, 128, 320};
    const float* W = t == 0 ? W0_ : t == 1 ? W1_ : t == 2 ? W2_ : W3_;
    const int K = tK[t], N = tN[t], Kp = tKp[t];
    int i = blockIdx.x * 256 + threadIdx.x;
    if (i >= N * Kp) return;
    int n = i / Kp, k = i - n * Kp;
    float v = (k < K) ? W[(size_t)k * N + n] : 0.0f;
    __nv_bfloat16 h = __float2bfloat16(v);
    const size_t off = (size_t)t * 400 * KP_MAX + i;
    wh[off] = h;
    wl[off] = __float2bfloat16(v - __bfloat162float(h));
}

// ---------------------------------------------------------------------------
// ELL build + rowsums
// ---------------------------------------------------------------------------
__global__ void ell_build4_kernel(const int* r0, const int* c0, const float* v0, int n0_,
                                  const int* r1, const int* c1, const float* v1, int n1_,
                                  const int* r2, const int* c2, const float* v2, int n2_,
                                  const int* r3, const int* c3, const float* v3, int n3_,
                                  float* evals, int* ecols, int* cnt) {
    const int w = blockIdx.y;
    const int* rows = w == 0 ? r0 : w == 1 ? r1 : w == 2 ? r2 : r3;
    const int* cols = w == 0 ? c0 : w == 1 ? c1 : w == 2 ? c2 : c3;
    const float* vals = w == 0 ? v0 : w == 1 ? v1 : w == 2 ? v2 : v3;
    const int nnz = w == 0 ? n0_ : w == 1 ? n1_ : w == 2 ? n2_ : n3_;
    float* ev = evals + (size_t)w * NNODES * ELL_CAP;
    int* ec = ecols + (size_t)w * NNODES * ELL_CAP;
    int* cn = cnt + w * NNODES;

    __shared__ int srows[MAX_NNZ];
    const int tid = threadIdx.x;
    const int nld = nnz < MAX_NNZ ? nnz : MAX_NNZ;
    for (int i = tid; i < nld; i += blockDim.x) srows[i] = rows[i];
    __syncthreads();

    const int e = blockIdx.x * blockDim.x + tid;
    if (e < nnz) {
        const int r = (e < MAX_NNZ) ? srows[e] : rows[e];
        int slot = 0;
        for (int k = 0; k < e && k < MAX_NNZ; k++) slot += (srows[k] == r);
        if (slot < ELL_CAP) {
            ev[r * ELL_CAP + slot] = vals[e];
            ec[r * ELL_CAP + slot] = cols[e];
            atomicMax(&cn[r], slot + 1);
        }
    }
}

__global__ void zero_cnt_kernel(int* cnt, int n) {
    int i = blockIdx.x * 256 + threadIdx.x;
    if (i < n) cnt[i] = 0;
}

__global__ void rowsum_kernel(const float* __restrict__ evals,
                              const int* __restrict__ cnt, float* __restrict__ srow) {
    int i = blockIdx.x * 256 + threadIdx.x;
    if (i >= 4 * NNODES) return;
    const int n = cnt[i];
    float s = 0.0f;
    for (int j = 0; j < n; j++) s += evals[(size_t)i * ELL_CAP + j];
    srow[i] = s;
}

// ---------------------------------------------------------------------------
// L0 pair (R14 form: separate gather + wide projection)
// ---------------------------------------------------------------------------
__global__ __launch_bounds__(256)
void spmm_in_kernel(const float* __restrict__ evals, const int* __restrict__ ecols,
                    const int* __restrict__ cnt, const float* __restrict__ H,
                    float* __restrict__ U0) {
    const int r = blockIdx.x;
    const int b = threadIdx.x;
    const int n = cnt[r];
    __shared__ float sv[ELL_CAP];
    __shared__ int   sc[ELL_CAP];
    if (b < n) { sv[b] = evals[r * ELL_CAP + b]; sc[b] = ecols[r * ELL_CAP + b]; }
    __syncthreads();
    float a0 = 0.0f, a1 = 0.0f;
    for (int j = 0; j < n; j++) {
        const float v = sv[j];
        const float2 h = *(const float2*)(H + ((size_t)b * NNODES + sc[j]) * 2);
        a0 = fmaf(v, h.x, a0);
        a1 = fmaf(v, h.y, a1);
    }
    *(float2*)(U0 + ((size_t)r * BATCH + b) * 2) = make_float2(a0, a1);
}

__global__ __launch_bounds__(256)
void l0_proj_kernel(const float* __restrict__ U0, const float* __restrict__ W0,
                    const float* __restrict__ bias, const float* __restrict__ srow,
                    __nv_bfloat16* __restrict__ Oh, __nv_bfloat16* __restrict__ Ol) {
    const int NF4 = KP_MAX / 4;
    const int p = blockIdx.x * 256 + threadIdx.x;
    if (p >= MROWS * NF4) return;
    const int m = p / NF4;
    const int f = (p - m * NF4) * 4;
    const float2 u = *(const float2*)(U0 + (size_t)m * 2);
    const float s = srow[m >> 8];
    float v[4];
    #pragma unroll
    for (int q = 0; q < 4; q++) {
        const int c = f + q;
        v[q] = (c < 400)
             ? fmaxf(fmaf(u.x, W0[c], fmaf(u.y, W0[400 + c], s * bias[c])), 0.0f)
             : 0.0f;
    }
    uint32_t lo0, lo1;
    uint32_t hi0 = split_pack_hi(v[0], v[1], lo0);
    uint32_t hi1 = split_pack_hi(v[2], v[3], lo1);
    const size_t o = (size_t)m * KP_MAX + f;
    *(uint2*)(Oh + o) = make_uint2(hi0, hi1);
    *(uint2*)(Ol + o) = make_uint2(lo0, lo1);
}

// ---------------------------------------------------------------------------
// L5 fused spmm + relu + transpose
// ---------------------------------------------------------------------------
__global__ __launch_bounds__(256)
void spmm_out_kernel(const float* __restrict__ evals, const int* __restrict__ ecols,
                     const int* __restrict__ cnt, const float* __restrict__ Y,
                     float* __restrict__ out) {
    const int r = blockIdx.x;
    const int b = threadIdx.x;
    const int n = cnt[r];
    __shared__ float sv[ELL_CAP];
    __shared__ int   sc[ELL_CAP];
    if (b < n) { sv[b] = evals[r * ELL_CAP + b]; sc[b] = ecols[r * ELL_CAP + b]; }
    __syncthreads();
    float a0 = 0.0f, a1 = 0.0f;
    for (int j = 0; j < n; j++) {
        const float v = sv[j];
        const float2 y = *(const float2*)(Y + ((size_t)sc[j] * BATCH + b) * 2);
        a0 = fmaf(v, y.x, a0);
        a1 = fmaf(v, y.y, a1);
    }
    *(float2*)(out + ((size_t)b * NNODES + r) * 2) =
        make_float2(fmaxf(a0, 0.0f), fmaxf(a1, 0.0f));
}

// ---------------------------------------------------------------------------
// Launch (R14 structure; GEMM has early-issue pipeline)
// ---------------------------------------------------------------------------
extern "C" void kernel_launch(void* const* d_in, const int* in_sizes, int n_in,
                              void* d_out, int out_size) {
    const float* H = (const float*)d_in[0];

    float *y, *xf, *sa, *evals, *rowsum;
    __nv_bfloat16 *uh, *ul, *wth, *wtl;
    int *ecols, *ecnt;
    cudaGetSymbolAddress((void**)&y,     g_y);
    cudaGetSymbolAddress((void**)&xf,    g_xf);
    cudaGetSymbolAddress((void**)&uh,    g_uh);
    cudaGetSymbolAddress((void**)&ul,    g_ul);
    cudaGetSymbolAddress((void**)&wth,   g_wth);
    cudaGetSymbolAddress((void**)&wtl,   g_wtl);
    cudaGetSymbolAddress((void**)&sa,    g_sa);
    cudaGetSymbolAddress((void**)&evals, g_ell_vals);
    cudaGetSymbolAddress((void**)&ecols, g_ell_cols);
    cudaGetSymbolAddress((void**)&ecnt,  g_ell_cnt);
    cudaGetSymbolAddress((void**)&rowsum, g_rowsum);

    const int SMEM_GEMM = NSTAGE * STAGE_B;   // 92160
    cudaFuncSetAttribute(gemm_bf16x3_mma<false>,
                         cudaFuncAttributeMaxDynamicSharedMemorySize, SMEM_GEMM);
    cudaFuncSetAttribute(gemm_bf16x3_mma<true>,
                         cudaFuncAttributeMaxDynamicSharedMemorySize, SMEM_GEMM);

    #define EV(a) (evals + (size_t)(a) * NNODES * ELL_CAP)
    #define EC(a) (ecols + (size_t)(a) * NNODES * ELL_CAP)
    #define EN(a) (ecnt + (a) * NNODES)
    #define RS(a) (rowsum + (a) * NNODES)
    #define WH(t) (wth + (size_t)(t) * 400 * KP_MAX)
    #define WL(t) (wtl + (size_t)(t) * 400 * KP_MAX)

    // Prep (R14 order)
    {
        dim3 grid(500, 4);
        wt_split4_kernel<<<grid, 256>>>(
            (const float*)d_in[15], (const float*)d_in[17],
            (const float*)d_in[19], (const float*)d_in[21], wth, wtl);
    }
    zero_cnt_kernel<<<(4 * NNODES + 255) / 256, 256>>>(ecnt, 4 * NNODES);
    {
        dim3 grid((MAX_NNZ + 255) / 256, 4);
        ell_build4_kernel<<<grid, 256>>>(
            (const int*)d_in[1], (const int*)d_in[2], (const float*)d_in[3], in_sizes[1],
            (const int*)d_in[4], (const int*)d_in[5], (const float*)d_in[6], in_sizes[4],
            (const int*)d_in[7], (const int*)d_in[8], (const float*)d_in[9], in_sizes[7],
            (const int*)d_in[10], (const int*)d_in[11], (const float*)d_in[12], in_sizes[10],
            evals, ecols, ecnt);
    }
    rowsum_kernel<<<(4 * NNODES + 255) / 256, 256>>>(evals, ecnt, rowsum);

    // --- L0 (Form I, sm_s): spmm on H; K=2 projection -> split U (Kp 416) ---
    spmm_in_kernel<<<NNODES, 256>>>(EV(0), EC(0), EN(0), H, sa);
    l0_proj_kernel<<<(MROWS * (KP_MAX / 4) + 255) / 256, 256>>>(
        sa, (const float*)d_in[13], (const float*)d_in[14], RS(0), uh, ul);

    // --- L1 (Form O, sm_s): GEMM -> y[.,300]; spmm+relu+split -> U (Kp 320) ---
    gemm_bf16x3_mma<false><<<dim3(5, 510), 256, SMEM_GEMM>>>(
        uh, ul, WH(0), WL(0), (const float*)d_in[16], nullptr, y, 300, 416);
    {
        dim3 grid((BATCH * (320 / 4) + 255) / 256, NNODES);
        spmm_f32_split_kernel<true><<<grid, 256>>>(EV(0), EC(0), EN(0),
                                                   y, 300, 300, 320, uh, ul);
    }

    // --- L2 (Form O, sm_t): GEMM -> y[.,100]; spmm+relu -> xf fp32 (stride 100) ---
    gemm_bf16x3_mma<false><<<dim3(2, 510), 256, SMEM_GEMM>>>(
        uh, ul, WH(1), WL(1), (const float*)d_in[18], nullptr, y, 100, 320);
    {
        dim3 grid((BATCH * (100 / 4) + 255) / 256, NNODES);
        spmm_relu_f32_kernel<<<grid, 256>>>(EV(1), EC(1), EN(1), y, 100, xf);
    }

    // --- L3 (Form I, sp_t): spmm fp32->split (Kp 128); GEMM -> xf (stride 300) ---
    {
        dim3 grid((BATCH * (128 / 4) + 255) / 256, NNODES);
        spmm_f32_split_kernel<false><<<grid, 256>>>(EV(3), EC(3), EN(3),
                                                    xf, 100, 100, 128, uh, ul);
    }
    gemm_bf16x3_mma<true><<<dim3(5, 510), 256, SMEM_GEMM>>>(
        uh, ul, WH(2), WL(2), (const float*)d_in[20], RS(3), xf, 300, 128);

    // --- L4 (Form I, sp_s): spmm fp32->split (Kp 320); GEMM -> xf (stride 400) ---
    {
        dim3 grid((BATCH * (320 / 4) + 255) / 256, NNODES);
        spmm_f32_split_kernel<false><<<grid, 256>>>(EV(2), EC(2), EN(2),
                                                    xf, 300, 300, 320, uh, ul);
    }
    gemm_bf16x3_mma<true><<<dim3(7, 510), 256, SMEM_GEMM>>>(
        uh, ul, WH(3), WL(3), (const float*)d_in[22], RS(2), xf, 400, 320);

    // --- L5: fp32 narrow GEMM -> sa[.,2]; fused spmm+relu+transpose ---
    l5_kernel<<<NNODES, 256>>>(xf, (const float*)d_in[23], (const float*)d_in[24], sa);
    spmm_out_kernel<<<NNODES, 256>>>(EV(2), EC(2), EN(2), sa, (float*)d_out);
}

// round 17
// speedup vs baseline: 1.0365x; 1.0365x over previous
#include <cuda_runtime.h>
#include <cuda_bf16.h>
#include <cstdint>

#define NNODES 255
#define BATCH  256
#define MROWS  (NNODES * BATCH)   // 65280
#define ELL_CAP 64
#define MAX_NNZ 2048
#define KP_MAX  416

// ---------------------------------------------------------------------------
// Scratch (no cudaMalloc allowed)
// ---------------------------------------------------------------------------
__device__ __align__(128) float          g_y   [MROWS * 304];        // Form-O GEMM out
__device__ __align__(128) float          g_xf  [MROWS * 400];        // fp32 activations
__device__ __align__(128) __nv_bfloat16  g_uh  [MROWS * KP_MAX];     // GEMM A hi
__device__ __align__(128) __nv_bfloat16  g_ul  [MROWS * KP_MAX];     // GEMM A lo
__device__ __align__(128) __nv_bfloat16  g_wth [4 * 400 * KP_MAX];
__device__ __align__(128) __nv_bfloat16  g_wtl [4 * 400 * KP_MAX];
__device__ __align__(128) float          g_sa  [MROWS * 2];
__device__ float g_ell_vals[4 * NNODES * ELL_CAP];
__device__ int   g_ell_cols[4 * NNODES * ELL_CAP];
__device__ int   g_ell_cnt [4 * NNODES];
__device__ float g_rowsum  [4 * NNODES];

// ---------------------------------------------------------------------------
// PTX helpers (family-neutral)
// ---------------------------------------------------------------------------
__device__ __forceinline__ uint32_t smem_u32(const void* p) {
    uint32_t a;
    asm("{ .reg .u64 t; cvta.to.shared.u64 t, %1; cvt.u32.u64 %0, t; }"
        : "=r"(a) : "l"(p));
    return a;
}
__device__ __forceinline__ void cp16(uint32_t dst, const void* src, uint32_t bytes) {
    asm volatile("cp.async.cg.shared.global [%0], [%1], 16, %2;"
                 :: "r"(dst), "l"(src), "r"(bytes) : "memory");
}
#define CP_COMMIT() asm volatile("cp.async.commit_group;" ::: "memory")
#define CP_WAIT(n)  asm volatile("cp.async.wait_group %0;" :: "n"(n) : "memory")

__device__ __forceinline__ void ldsm4(uint32_t* r, uint32_t addr) {
    asm volatile("ldmatrix.sync.aligned.m8n8.x4.shared.b16 {%0,%1,%2,%3}, [%4];"
                 : "=r"(r[0]), "=r"(r[1]), "=r"(r[2]), "=r"(r[3]) : "r"(addr));
}
__device__ __forceinline__ void ldsm2(uint32_t* r, uint32_t addr) {
    asm volatile("ldmatrix.sync.aligned.m8n8.x2.shared.b16 {%0,%1}, [%2];"
                 : "=r"(r[0]), "=r"(r[1]) : "r"(addr));
}
__device__ __forceinline__ void mma16816(float* c, const uint32_t* a, const uint32_t* b) {
    asm volatile("mma.sync.aligned.m16n8k16.row.col.f32.bf16.bf16.f32 "
                 "{%0,%1,%2,%3}, {%4,%5,%6,%7}, {%8,%9}, {%0,%1,%2,%3};"
                 : "+f"(c[0]), "+f"(c[1]), "+f"(c[2]), "+f"(c[3])
                 : "r"(a[0]), "r"(a[1]), "r"(a[2]), "r"(a[3]), "r"(b[0]), "r"(b[1]));
}
__device__ __forceinline__ uint32_t split_pack_hi(float v0, float v1, uint32_t& lo_bits) {
    __nv_bfloat162 h = __floats2bfloat162_rn(v0, v1);
    float2 hf = __bfloat1622float2(h);
    __nv_bfloat162 l = __floats2bfloat162_rn(v0 - hf.x, v1 - hf.y);
    lo_bits = *reinterpret_cast<uint32_t*>(&l);
    return *reinterpret_cast<uint32_t*>(&h);
}

// ---------------------------------------------------------------------------
// bf16x3 HMMA GEMM (R14 config, measured best): CTA 128x64x32, 256 thr /
// 8 warps (4m x 2n), warp 32x32, 3-stage cp.async pipeline (loads issued
// AFTER compute — measured faster than early-issue), 2 CTAs/SM.
// FORMI=false: Y = A@B^T + bias ; FORMI=true: Y = relu(A@B^T + s[node]*bias).
// ---------------------------------------------------------------------------
#define BM 128
#define BN 64
#define LDT 40
#define MAT_A (128 * LDT * 2)          // 10240
#define MAT_Bt (64 * LDT * 2)          // 5120
#define STAGE_B (2 * MAT_A + 2 * MAT_Bt)   // 30720
#define NSTAGE 3

template <bool FORMI>
__global__ __launch_bounds__(256, 2)
void gemm_bf16x3_mma(const __nv_bfloat16* __restrict__ Ah,
                     const __nv_bfloat16* __restrict__ Al,
                     const __nv_bfloat16* __restrict__ Bh,
                     const __nv_bfloat16* __restrict__ Bl,
                     const float* __restrict__ bias,
                     const float* __restrict__ srow,
                     float* __restrict__ Y,
                     int Nfull, int Kp) {
    extern __shared__ __align__(128) char smem[];
    const uint32_t sb = smem_u32(smem);

    const int tid  = threadIdx.x;
    const int lane = tid & 31;
    const int wid  = tid >> 5;
    const int wm   = wid & 3;
    const int wn   = wid >> 2;
    const int m0   = blockIdx.y * BM;
    const int n0   = blockIdx.x * BN;

    const int nblk = Kp >> 5;

    auto load_stage = [&](int blk, int slot) {
        const int k0 = blk << 5;
        const uint32_t sdst = sb + slot * STAGE_B;
        #pragma unroll
        for (int i = 0; i < 6; i++) {
            const int idx = i * 256 + tid;          // 0..1535
            if (idx < 1024) {
                const int mat = idx >> 9;
                const int c   = idx & 511;
                const int row = c >> 2;
                const int seg = c & 3;
                const uint32_t dst = sdst + mat * MAT_A + (row * LDT + seg * 8) * 2;
                const __nv_bfloat16* src = (mat == 0 ? Ah : Al);
                cp16(dst, src + (size_t)(m0 + row) * Kp + k0 + seg * 8, 16);
            } else {
                const int j   = idx - 1024;
                const int mat = j >> 8;
                const int c   = j & 255;
                const int row = c >> 2;
                const int seg = c & 3;
                const uint32_t dst = sdst + 2 * MAT_A + mat * MAT_Bt +
                                     (row * LDT + seg * 8) * 2;
                const __nv_bfloat16* src = (mat == 0 ? Bh : Bl);
                const int gr = n0 + row;
                const int ok = gr < Nfull;
                cp16(dst, src + (size_t)(ok ? gr : 0) * Kp + k0 + seg * 8, ok ? 16 : 0);
            }
        }
        CP_COMMIT();
    };

    float acc[2][4][4];
    #pragma unroll
    for (int i = 0; i < 2; i++)
        #pragma unroll
        for (int j = 0; j < 4; j++)
            #pragma unroll
            for (int q = 0; q < 4; q++) acc[i][j][q] = 0.0f;

    #pragma unroll
    for (int s = 0; s < NSTAGE - 1; s++)
        if (s < nblk) load_stage(s, s);

    for (int blk = 0; blk < nblk; blk++) {
        int slot = blk % NSTAGE;
        if (blk + 1 < nblk) CP_WAIT(1);
        else                CP_WAIT(0);
        __syncthreads();

        const uint32_t stage = sb + slot * STAGE_B;
        #pragma unroll
        for (int ks = 0; ks < 32; ks += 16) {
            uint32_t ah[2][4], al[2][4], bh[4][2], bl[4][2];
            const int arow = wm * 32 + (lane & 15);
            const int akoff = ks + ((lane >> 4) << 3);
            #pragma unroll
            for (int mi = 0; mi < 2; mi++) {
                const uint32_t off = ((arow + mi * 16) * LDT + akoff) * 2;
                ldsm4(ah[mi], stage + off);
                ldsm4(al[mi], stage + MAT_A + off);
            }
            const int brow = wn * 32 + (lane & 7);
            const int bkoff = ks + (((lane >> 3) & 1) << 3);
            #pragma unroll
            for (int ni = 0; ni < 4; ni++) {
                const uint32_t off = ((brow + ni * 8) * LDT + bkoff) * 2;
                ldsm2(bh[ni], stage + 2 * MAT_A + off);
                ldsm2(bl[ni], stage + 2 * MAT_A + MAT_Bt + off);
            }
            #pragma unroll
            for (int mi = 0; mi < 2; mi++)
                #pragma unroll
                for (int ni = 0; ni < 4; ni++) {
                    mma16816(acc[mi][ni], ah[mi], bh[ni]);
                    mma16816(acc[mi][ni], ah[mi], bl[ni]);
                    mma16816(acc[mi][ni], al[mi], bh[ni]);
                }
        }

        const int nx = blk + NSTAGE - 1;
        if (nx < nblk) load_stage(nx, nx % NSTAGE);
    }

    const float s = FORMI ? srow[m0 >> 8] : 0.0f;
    #pragma unroll
    for (int ni = 0; ni < 4; ni++) {
        const int gc = n0 + wn * 32 + ni * 8 + (lane & 3) * 2;
        if (gc >= Nfull) continue;
        const float b0 = FORMI ? s * bias[gc]     : bias[gc];
        const float b1 = FORMI ? s * bias[gc + 1] : bias[gc + 1];
        #pragma unroll
        for (int mi = 0; mi < 2; mi++) {
            const int gr = m0 + wm * 32 + mi * 16 + (lane >> 2);
            float2 v0 = make_float2(acc[mi][ni][0] + b0, acc[mi][ni][1] + b1);
            float2 v1 = make_float2(acc[mi][ni][2] + b0, acc[mi][ni][3] + b1);
            if (FORMI) {
                v0.x = fmaxf(v0.x, 0.f); v0.y = fmaxf(v0.y, 0.f);
                v1.x = fmaxf(v1.x, 0.f); v1.y = fmaxf(v1.y, 0.f);
            }
            *(float2*)(Y + (size_t)gr * Nfull + gc) = v0;
            *(float2*)(Y + (size_t)(gr + 8) * Nfull + gc) = v1;
        }
    }
}

// ---------------------------------------------------------------------------
// Gather spmm (fp32 in) -> split bf16 out
// ---------------------------------------------------------------------------
template <bool RELU>
__global__ __launch_bounds__(256)
void spmm_f32_split_kernel(const float* __restrict__ evals, const int* __restrict__ ecols,
                           const int* __restrict__ cnt, const float* __restrict__ X,
                           int din, int dis, int kp,
                           __nv_bfloat16* __restrict__ uh, __nv_bfloat16* __restrict__ ul) {
    const int r = blockIdx.y;
    const int n = cnt[r];
    __shared__ float sv[ELL_CAP];
    __shared__ int   sc[ELL_CAP];
    if (threadIdx.x < n) {
        sv[threadIdx.x] = evals[r * ELL_CAP + threadIdx.x];
        sc[threadIdx.x] = ecols[r * ELL_CAP + threadIdx.x];
    }
    __syncthreads();

    const int nF4 = kp >> 2;
    const int p = blockIdx.x * 256 + threadIdx.x;
    if (p >= BATCH * nF4) return;
    const int b = p / nF4, f = (p - b * nF4) * 4;
    const size_t obase = ((size_t)r * BATCH + b) * kp + f;

    if (f >= din) {
        *(uint2*)(uh + obase) = make_uint2(0, 0);
        *(uint2*)(ul + obase) = make_uint2(0, 0);
        return;
    }
    float4 acc = make_float4(0.f, 0.f, 0.f, 0.f);
    for (int j = 0; j < n; j++) {
        const float a = sv[j];
        const float4 x = *(const float4*)(X + ((size_t)sc[j] * BATCH + b) * dis + f);
        acc.x = fmaf(a, x.x, acc.x);
        acc.y = fmaf(a, x.y, acc.y);
        acc.z = fmaf(a, x.z, acc.z);
        acc.w = fmaf(a, x.w, acc.w);
    }
    if (RELU) {
        acc.x = fmaxf(acc.x, 0.f); acc.y = fmaxf(acc.y, 0.f);
        acc.z = fmaxf(acc.z, 0.f); acc.w = fmaxf(acc.w, 0.f);
    }
    uint32_t lo0, lo1;
    uint32_t hi0 = split_pack_hi(acc.x, acc.y, lo0);
    uint32_t hi1 = split_pack_hi(acc.z, acc.w, lo1);
    *(uint2*)(uh + obase) = make_uint2(hi0, hi1);
    *(uint2*)(ul + obase) = make_uint2(lo0, lo1);
}

// ---------------------------------------------------------------------------
// Gather spmm fp32 -> fp32 (+relu)
// ---------------------------------------------------------------------------
__global__ __launch_bounds__(256)
void spmm_relu_f32_kernel(const float* __restrict__ evals, const int* __restrict__ ecols,
                          const int* __restrict__ cnt, const float* __restrict__ Y,
                          int din, float* __restrict__ Xo) {
    const int r = blockIdx.y;
    const int n = cnt[r];
    __shared__ float sv[ELL_CAP];
    __shared__ int   sc[ELL_CAP];
    if (threadIdx.x < n) {
        sv[threadIdx.x] = evals[r * ELL_CAP + threadIdx.x];
        sc[threadIdx.x] = ecols[r * ELL_CAP + threadIdx.x];
    }
    __syncthreads();

    const int nF4 = din >> 2;
    const int p = blockIdx.x * 256 + threadIdx.x;
    if (p >= BATCH * nF4) return;
    const int b = p / nF4, f = (p - b * nF4) * 4;

    float4 acc = make_float4(0.f, 0.f, 0.f, 0.f);
    for (int j = 0; j < n; j++) {
        const float a = sv[j];
        const float4 x = *(const float4*)(Y + ((size_t)sc[j] * BATCH + b) * din + f);
        acc.x = fmaf(a, x.x, acc.x);
        acc.y = fmaf(a, x.y, acc.y);
        acc.z = fmaf(a, x.z, acc.z);
        acc.w = fmaf(a, x.w, acc.w);
    }
    acc.x = fmaxf(acc.x, 0.f); acc.y = fmaxf(acc.y, 0.f);
    acc.z = fmaxf(acc.z, 0.f); acc.w = fmaxf(acc.w, 0.f);
    *(float4*)(Xo + ((size_t)r * BATCH + b) * din + f) = acc;
}

// ---------------------------------------------------------------------------
// L5: Y[m,0:2] = xf[m, 0:400] @ Wd2[400,2] + bd2
// ---------------------------------------------------------------------------
__global__ __launch_bounds__(256)
void l5_kernel(const float* __restrict__ xf,
               const float* __restrict__ W, const float* __restrict__ bias,
               float* __restrict__ Y) {
    __shared__ float2 Ws[400];
    for (int i = threadIdx.x; i < 400; i += 256)
        Ws[i] = make_float2(W[i * 2], W[i * 2 + 1]);
    __syncthreads();

    const int m = blockIdx.x * 256 + threadIdx.x;
    const float* px = xf + (size_t)m * 400;
    float a0 = bias[0], a1 = bias[1];
    #pragma unroll 4
    for (int k = 0; k < 400; k += 4) {
        const float4 x = *(const float4*)(px + k);
        const float2 w0 = Ws[k], w1 = Ws[k + 1], w2 = Ws[k + 2], w3 = Ws[k + 3];
        a0 = fmaf(x.x, w0.x, a0); a1 = fmaf(x.x, w0.y, a1);
        a0 = fmaf(x.y, w1.x, a0); a1 = fmaf(x.y, w1.y, a1);
        a0 = fmaf(x.z, w2.x, a0); a1 = fmaf(x.z, w2.y, a1);
        a0 = fmaf(x.w, w3.x, a0); a1 = fmaf(x.w, w3.y, a1);
    }
    *(float2*)(Y + (size_t)m * 2) = make_float2(a0, a1);
}

// ---------------------------------------------------------------------------
// Weight prep + cnt zeroing (one launch; y<4 -> weight t, y==4 -> zero cnt)
// ---------------------------------------------------------------------------
__global__ void wt_split4_kernel(const float* W0_, const float* W1_,
                                 const float* W2_, const float* W3_,
                                 __nv_bfloat16* __restrict__ wh,
                                 __nv_bfloat16* __restrict__ wl,
                                 int* __restrict__ cnt) {
    if (blockIdx.y == 4) {
        int i = blockIdx.x * 256 + threadIdx.x;
        if (i < 4 * NNODES) cnt[i] = 0;
        return;
    }
    const int t = blockIdx.y;
    const int tK[4]  = {400, 300, 100, 300};
    const int tN[4]  = {300, 100, 300, 400};
    const int tKp[4] = {416, 320, 128, 320};
    const float* W = t == 0 ? W0_ : t == 1 ? W1_ : t == 2 ? W2_ : W3_;
    const int K = tK[t], N = tN[t], Kp = tKp[t];
    int i = blockIdx.x * 256 + threadIdx.x;
    if (i >= N * Kp) return;
    int n = i / Kp, k = i - n * Kp;
    float v = (k < K) ? W[(size_t)k * N + n] : 0.0f;
    __nv_bfloat16 h = __float2bfloat16(v);
    const size_t off = (size_t)t * 400 * KP_MAX + i;
    wh[off] = h;
    wl[off] = __float2bfloat16(v - __bfloat162float(h));
}

// ---------------------------------------------------------------------------
// ELL build + rowsums
// ---------------------------------------------------------------------------
__global__ void ell_build4_kernel(const int* r0, const int* c0, const float* v0, int n0_,
                                  const int* r1, const int* c1, const float* v1, int n1_,
                                  const int* r2, const int* c2, const float* v2, int n2_,
                                  const int* r3, const int* c3, const float* v3, int n3_,
                                  float* evals, int* ecols, int* cnt) {
    const int w = blockIdx.y;
    const int* rows = w == 0 ? r0 : w == 1 ? r1 : w == 2 ? r2 : r3;
    const int* cols = w == 0 ? c0 : w == 1 ? c1 : w == 2 ? c2 : c3;
    const float* vals = w == 0 ? v0 : w == 1 ? v1 : w == 2 ? v2 : v3;
    const int nnz = w == 0 ? n0_ : w == 1 ? n1_ : w == 2 ? n2_ : n3_;
    float* ev = evals + (size_t)w * NNODES * ELL_CAP;
    int* ec = ecols + (size_t)w * NNODES * ELL_CAP;
    int* cn = cnt + w * NNODES;

    __shared__ int srows[MAX_NNZ];
    const int tid = threadIdx.x;
    const int nld = nnz < MAX_NNZ ? nnz : MAX_NNZ;
    for (int i = tid; i < nld; i += blockDim.x) srows[i] = rows[i];
    __syncthreads();

    const int e = blockIdx.x * blockDim.x + tid;
    if (e < nnz) {
        const int r = (e < MAX_NNZ) ? srows[e] : rows[e];
        int slot = 0;
        for (int k = 0; k < e && k < MAX_NNZ; k++) slot += (srows[k] == r);
        if (slot < ELL_CAP) {
            ev[r * ELL_CAP + slot] = vals[e];
            ec[r * ELL_CAP + slot] = cols[e];
            atomicMax(&cn[r], slot + 1);
        }
    }
}

__global__ void rowsum_kernel(const float* __restrict__ evals,
                              const int* __restrict__ cnt, float* __restrict__ srow) {
    int i = blockIdx.x * 256 + threadIdx.x;
    if (i >= 4 * NNODES) return;
    const int n = cnt[i];
    float s = 0.0f;
    for (int j = 0; j < n; j++) s += evals[(size_t)i * ELL_CAP + j];
    srow[i] = s;
}

// ---------------------------------------------------------------------------
// L0 pair (separate gather + wide projection)
// ---------------------------------------------------------------------------
__global__ __launch_bounds__(256)
void spmm_in_kernel(const float* __restrict__ evals, const int* __restrict__ ecols,
                    const int* __restrict__ cnt, const float* __restrict__ H,
                    float* __restrict__ U0) {
    const int r = blockIdx.x;
    const int b = threadIdx.x;
    const int n = cnt[r];
    __shared__ float sv[ELL_CAP];
    __shared__ int   sc[ELL_CAP];
    if (b < n) { sv[b] = evals[r * ELL_CAP + b]; sc[b] = ecols[r * ELL_CAP + b]; }
    __syncthreads();
    float a0 = 0.0f, a1 = 0.0f;
    for (int j = 0; j < n; j++) {
        const float v = sv[j];
        const float2 h = *(const float2*)(H + ((size_t)b * NNODES + sc[j]) * 2);
        a0 = fmaf(v, h.x, a0);
        a1 = fmaf(v, h.y, a1);
    }
    *(float2*)(U0 + ((size_t)r * BATCH + b) * 2) = make_float2(a0, a1);
}

__global__ __launch_bounds__(256)
void l0_proj_kernel(const float* __restrict__ U0, const float* __restrict__ W0,
                    const float* __restrict__ bias, const float* __restrict__ srow,
                    __nv_bfloat16* __restrict__ Oh, __nv_bfloat16* __restrict__ Ol) {
    const int NF4 = KP_MAX / 4;
    const int p = blockIdx.x * 256 + threadIdx.x;
    if (p >= MROWS * NF4) return;
    const int m = p / NF4;
    const int f = (p - m * NF4) * 4;
    const float2 u = *(const float2*)(U0 + (size_t)m * 2);
    const float s = srow[m >> 8];
    float v[4];
    #pragma unroll
    for (int q = 0; q < 4; q++) {
        const int c = f + q;
        v[q] = (c < 400)
             ? fmaxf(fmaf(u.x, W0[c], fmaf(u.y, W0[400 + c], s * bias[c])), 0.0f)
             : 0.0f;
    }
    uint32_t lo0, lo1;
    uint32_t hi0 = split_pack_hi(v[0], v[1], lo0);
    uint32_t hi1 = split_pack_hi(v[2], v[3], lo1);
    const size_t o = (size_t)m * KP_MAX + f;
    *(uint2*)(Oh + o) = make_uint2(hi0, hi1);
    *(uint2*)(Ol + o) = make_uint2(lo0, lo1);
}

// ---------------------------------------------------------------------------
// L5 fused spmm + relu + transpose
// ---------------------------------------------------------------------------
__global__ __launch_bounds__(256)
void spmm_out_kernel(const float* __restrict__ evals, const int* __restrict__ ecols,
                     const int* __restrict__ cnt, const float* __restrict__ Y,
                     float* __restrict__ out) {
    const int r = blockIdx.x;
    const int b = threadIdx.x;
    const int n = cnt[r];
    __shared__ float sv[ELL_CAP];
    __shared__ int   sc[ELL_CAP];
    if (b < n) { sv[b] = evals[r * ELL_CAP + b]; sc[b] = ecols[r * ELL_CAP + b]; }
    __syncthreads();
    float a0 = 0.0f, a1 = 0.0f;
    for (int j = 0; j < n; j++) {
        const float v = sv[j];
        const float2 y = *(const float2*)(Y + ((size_t)sc[j] * BATCH + b) * 2);
        a0 = fmaf(v, y.x, a0);
        a1 = fmaf(v, y.y, a1);
    }
    *(float2*)(out + ((size_t)b * NNODES + r) * 2) =
        make_float2(fmaxf(a0, 0.0f), fmaxf(a1, 0.0f));
}

// ---------------------------------------------------------------------------
// Launch (R14 structure; zero_cnt folded into wt_split4)
// ---------------------------------------------------------------------------
extern "C" void kernel_launch(void* const* d_in, const int* in_sizes, int n_in,
                              void* d_out, int out_size) {
    const float* H = (const float*)d_in[0];

    float *y, *xf, *sa, *evals, *rowsum;
    __nv_bfloat16 *uh, *ul, *wth, *wtl;
    int *ecols, *ecnt;
    cudaGetSymbolAddress((void**)&y,     g_y);
    cudaGetSymbolAddress((void**)&xf,    g_xf);
    cudaGetSymbolAddress((void**)&uh,    g_uh);
    cudaGetSymbolAddress((void**)&ul,    g_ul);
    cudaGetSymbolAddress((void**)&wth,   g_wth);
    cudaGetSymbolAddress((void**)&wtl,   g_wtl);
    cudaGetSymbolAddress((void**)&sa,    g_sa);
    cudaGetSymbolAddress((void**)&evals, g_ell_vals);
    cudaGetSymbolAddress((void**)&ecols, g_ell_cols);
    cudaGetSymbolAddress((void**)&ecnt,  g_ell_cnt);
    cudaGetSymbolAddress((void**)&rowsum, g_rowsum);

    const int SMEM_GEMM = NSTAGE * STAGE_B;   // 92160
    cudaFuncSetAttribute(gemm_bf16x3_mma<false>,
                         cudaFuncAttributeMaxDynamicSharedMemorySize, SMEM_GEMM);
    cudaFuncSetAttribute(gemm_bf16x3_mma<true>,
                         cudaFuncAttributeMaxDynamicSharedMemorySize, SMEM_GEMM);

    #define EV(a) (evals + (size_t)(a) * NNODES * ELL_CAP)
    #define EC(a) (ecols + (size_t)(a) * NNODES * ELL_CAP)
    #define EN(a) (ecnt + (a) * NNODES)
    #define RS(a) (rowsum + (a) * NNODES)
    #define WH(t) (wth + (size_t)(t) * 400 * KP_MAX)
    #define WL(t) (wtl + (size_t)(t) * 400 * KP_MAX)

    // Prep: (weight split x4 + cnt zero) -> ell build -> rowsum
    {
        dim3 grid(500, 5);
        wt_split4_kernel<<<grid, 256>>>(
            (const float*)d_in[15], (const float*)d_in[17],
            (const float*)d_in[19], (const float*)d_in[21], wth, wtl, ecnt);
    }
    {
        dim3 grid((MAX_NNZ + 255) / 256, 4);
        ell_build4_kernel<<<grid, 256>>>(
            (const int*)d_in[1], (const int*)d_in[2], (const float*)d_in[3], in_sizes[1],
            (const int*)d_in[4], (const int*)d_in[5], (const float*)d_in[6], in_sizes[4],
            (const int*)d_in[7], (const int*)d_in[8], (const float*)d_in[9], in_sizes[7],
            (const int*)d_in[10], (const int*)d_in[11], (const float*)d_in[12], in_sizes[10],
            evals, ecols, ecnt);
    }
    rowsum_kernel<<<(4 * NNODES + 255) / 256, 256>>>(evals, ecnt, rowsum);

    // --- L0 (Form I, sm_s): spmm on H; K=2 projection -> split U (Kp 416) ---
    spmm_in_kernel<<<NNODES, 256>>>(EV(0), EC(0), EN(0), H, sa);
    l0_proj_kernel<<<(MROWS * (KP_MAX / 4) + 255) / 256, 256>>>(
        sa, (const float*)d_in[13], (const float*)d_in[14], RS(0), uh, ul);

    // --- L1 (Form O, sm_s): GEMM -> y[.,300]; spmm+relu+split -> U (Kp 320) ---
    gemm_bf16x3_mma<false><<<dim3(5, 510), 256, SMEM_GEMM>>>(
        uh, ul, WH(0), WL(0), (const float*)d_in[16], nullptr, y, 300, 416);
    {
        dim3 grid((BATCH * (320 / 4) + 255) / 256, NNODES);
        spmm_f32_split_kernel<true><<<grid, 256>>>(EV(0), EC(0), EN(0),
                                                   y, 300, 300, 320, uh, ul);
    }

    // --- L2 (Form O, sm_t): GEMM -> y[.,100]; spmm+relu -> xf fp32 (stride 100) ---
    gemm_bf16x3_mma<false><<<dim3(2, 510), 256, SMEM_GEMM>>>(
        uh, ul, WH(1), WL(1), (const float*)d_in[18], nullptr, y, 100, 320);
    {
        dim3 grid((BATCH * (100 / 4) + 255) / 256, NNODES);
        spmm_relu_f32_kernel<<<grid, 256>>>(EV(1), EC(1), EN(1), y, 100, xf);
    }

    // --- L3 (Form I, sp_t): spmm fp32->split (Kp 128); GEMM -> xf (stride 300) ---
    {
        dim3 grid((BATCH * (128 / 4) + 255) / 256, NNODES);
        spmm_f32_split_kernel<false><<<grid, 256>>>(EV(3), EC(3), EN(3),
                                                    xf, 100, 100, 128, uh, ul);
    }
    gemm_bf16x3_mma<true><<<dim3(5, 510), 256, SMEM_GEMM>>>(
        uh, ul, WH(2), WL(2), (const float*)d_in[20], RS(3), xf, 300, 128);

    // --- L4 (Form I, sp_s): spmm fp32->split (Kp 320); GEMM -> xf (stride 400) ---
    {
        dim3 grid((BATCH * (320 / 4) + 255) / 256, NNODES);
        spmm_f32_split_kernel<false><<<grid, 256>>>(EV(2), EC(2), EN(2),
                                                    xf, 300, 300, 320, uh, ul);
    }
    gemm_bf16x3_mma<true><<<dim3(7, 510), 256, SMEM_GEMM>>>(
        uh, ul, WH(3), WL(3), (const float*)d_in[22], RS(2), xf, 400, 320);

    // --- L5: fp32 narrow GEMM -> sa[.,2]; fused spmm+relu+transpose ---
    l5_kernel<<<NNODES, 256>>>(xf, (const float*)d_in[23], (const float*)d_in[24], sa);
    spmm_out_kernel<<<NNODES, 256>>>(EV(2), EC(2), EN(2), sa, (float*)d_out);
}